// round 12
// baseline (speedup 1.0000x reference)
#include <cuda_runtime.h>
#include <cstdint>

// Problem constants
#define Bn   32
#define Cn   128
#define Tn   8192
#define Kn   5
#define MCn  256
#define KTOT (Cn * Kn)        // 640
#define KC   32               // K per chunk
#define NCHUNK (KTOT / KC)    // 20
#define BT   256              // t per block tile
#define NBLK (Tn / BT)        // 32

// SMEM: A two buffers (hi+lo planes, 32KB each buf) @0, @32768
//       B planes: hi @65536 (32KB), lo @98304 (32KB)
#define SMEM_BYTES 131072

// Scratch
__device__ float g_gap[Bn * Cn];
__device__ float g_h[Bn * MCn];
// A tiles: [b][chunk][plane hi/lo][k(32)][o(128)] floats, o pre-XOR-swizzled
__device__ float g_wa[(size_t)Bn * NCHUNK * 2 * KC * 128];

// ---------------- helpers ----------------
__device__ __forceinline__ void split_tf32(float v, uint32_t& hi, uint32_t& lo) {
    uint32_t h;
    asm("cvt.rna.tf32.f32 %0, %1;" : "=r"(h) : "f"(v));
    float l = v - __uint_as_float(h);
    asm("cvt.rna.tf32.f32 %0, %1;" : "=r"(lo) : "f"(l));
    hi = h;
}
__device__ __forceinline__ void mma_tf32(float* d, const uint32_t a[4],
                                         uint32_t b0, uint32_t b1) {
    asm volatile(
        "mma.sync.aligned.m16n8k8.row.col.f32.tf32.tf32.f32 "
        "{%0,%1,%2,%3}, {%4,%5,%6,%7}, {%8,%9}, {%0,%1,%2,%3};"
        : "+f"(d[0]), "+f"(d[1]), "+f"(d[2]), "+f"(d[3])
        : "r"(a[0]), "r"(a[1]), "r"(a[2]), "r"(a[3]), "r"(b0), "r"(b1));
}

// ---------------------------------------------------------------------------
// Stage 1: masked global average pool.
// ---------------------------------------------------------------------------
__global__ void gap_kernel(const float* __restrict__ x, const int* __restrict__ lens) {
    int bc = blockIdx.x;
    const float4* row = reinterpret_cast<const float4*>(x + (size_t)bc * Tn);
    float s = 0.f;
    for (int i = threadIdx.x; i < Tn / 4; i += blockDim.x) {
        float4 v = row[i];
        s += (v.x + v.y) + (v.z + v.w);
    }
    for (int o = 16; o; o >>= 1) s += __shfl_down_sync(0xffffffffu, s, o);
    __shared__ float sm[8];
    int w = threadIdx.x >> 5, l = threadIdx.x & 31;
    if (l == 0) sm[w] = s;
    __syncthreads();
    if (threadIdx.x == 0) {
        float tot = 0.f;
        #pragma unroll
        for (int i = 0; i < 8; i++) tot += sm[i];
        g_gap[bc] = tot / (float)lens[bc / Cn];
    }
}

// ---------------------------------------------------------------------------
// Stage 2: h = sigmoid(gap @ w1^T + b1)
// ---------------------------------------------------------------------------
__global__ void fc1_kernel(const float* __restrict__ w1, const float* __restrict__ b1) {
    int b = blockIdx.x;
    __shared__ float sg[Cn];
    if (threadIdx.x < Cn) sg[threadIdx.x] = g_gap[b * Cn + threadIdx.x];
    __syncthreads();
    int j = threadIdx.x;
    const float* wr = w1 + (size_t)j * Cn;
    float z = b1[j];
    #pragma unroll 8
    for (int c = 0; c < Cn; c++) z += sg[c] * wr[c];
    g_h[b * MCn + j] = 1.f / (1.f + expf(-z));
}

// ---------------------------------------------------------------------------
// Stage 2.5: dynamic weights -> tf32 hi/lo planes, XOR-swizzled o index.
// One thread per (b,c,k,o):  idx = ((b*20+c)*32+k)*128 + o
// ---------------------------------------------------------------------------
__global__ void wd_kernel(const float* __restrict__ w2) {
    int idx = blockIdx.x * 256 + threadIdx.x;
    int o = idx & 127;
    int r = idx >> 7;
    int k = r & 31; r >>= 5;
    int c = r % NCHUNK;
    int b = r / NCHUNK;
    int ik = c * KC + k;
    int i  = ik / 5;
    float v = w2[o * KTOT + ik] * g_h[b * MCn + 2 * o + (i >= 64 ? 1 : 0)];
    uint32_t hi, lo;
    split_tf32(v, hi, lo);
    int col = o ^ ((k & 3) << 3);
    float* base = g_wa + ((size_t)(b * NCHUNK + c) * 2) * (KC * 128);
    base[k * 128 + col]            = __uint_as_float(hi);
    base[KC * 128 + k * 128 + col] = __uint_as_float(lo);
}

// ---------------------------------------------------------------------------
// Stage 3: implicit-GEMM conv via mma.sync tf32 (3xTF32).
// Block: 128 o x 256 t, 8 warps of 64 o x 64 t. 20 K-chunks of 32.
// ---------------------------------------------------------------------------
__global__ void __launch_bounds__(256, 1)
conv_kernel(const float* __restrict__ x, float* __restrict__ out) {
    extern __shared__ __align__(16) float smem[];
    float* sA  = smem;               // [2][2 planes][32][128]
    float* sBh = smem + 16384;       // [32][256]
    float* sBl = smem + 24576;       // [32][256]

    const int tid = threadIdx.x;
    const int t0 = blockIdx.x * BT;
    const int b  = blockIdx.y;
    const int w  = tid >> 5, lane = tid & 31;
    const int g  = lane >> 2, tig = lane & 3;
    const int m0 = (w & 1) * 64;
    const int n0 = (w >> 1) * 64;
    const uint32_t xr = (uint32_t)(tig << 3);

    const float* xb   = x + (size_t)b * Cn * Tn;
    const float* wa_b = g_wa + (size_t)b * NCHUNK * 2 * KC * 128;

    float acc[4][8][4];
    #pragma unroll
    for (int mt = 0; mt < 4; mt++)
        #pragma unroll
        for (int nt = 0; nt < 8; nt++)
            #pragma unroll
            for (int q = 0; q < 4; q++) acc[mt][nt][q] = 0.f;

    // B-build mapping
    const int bks  = tid >> 3;        // 0..31  (k row)
    const int bseg = tid & 7;         // 0..7   (32-t segment)

    // prefetch A chunk 0
    {
        const float4* src = reinterpret_cast<const float4*>(wa_b);
        #pragma unroll
        for (int e = 0; e < 8; e++) {
            uint32_t du;
            asm("{ .reg .u64 t; cvta.to.shared.u64 t, %1; cvt.u32.u64 %0, t; }"
                : "=r"(du) : "l"(sA + (e * 256 + tid) * 4));
            asm volatile("cp.async.cg.shared.global [%0], [%1], 16;"
                         :: "r"(du), "l"(src + e * 256 + tid) : "memory");
        }
        asm volatile("cp.async.commit_group;" ::: "memory");
    }

    for (int c = 0; c < NCHUNK; c++) {
        const int buf = c & 1;
        // prefetch next A chunk
        if (c + 1 < NCHUNK) {
            const float4* src = reinterpret_cast<const float4*>(
                wa_b + (size_t)(c + 1) * 2 * KC * 128);
            float* dst = sA + ((c + 1) & 1) * 8192;
            #pragma unroll
            for (int e = 0; e < 8; e++) {
                uint32_t du;
                asm("{ .reg .u64 t; cvta.to.shared.u64 t, %1; cvt.u32.u64 %0, t; }"
                    : "=r"(du) : "l"(dst + (e * 256 + tid) * 4));
                asm volatile("cp.async.cg.shared.global [%0], [%1], 16;"
                             :: "r"(du), "l"(src + e * 256 + tid) : "memory");
            }
            asm volatile("cp.async.commit_group;" ::: "memory");
        }

        // build B chunk: 32 k x 256 t, hi/lo planes, col = t ^ ((k&3)<<3)
        {
            int ik = c * KC + bks;
            int i  = ik / 5;
            int kk = ik - i * 5;
            const float* src = xb + (size_t)i * Tn;
            int tb = t0 + bseg * 32 + kk - 2;
            int xk = (bks & 3) << 3;
            float* ph = sBh + bks * 256;
            float* pl = sBl + bks * 256;
            #pragma unroll
            for (int q8 = 0; q8 < 4; q8++) {
                float hv[8], lv[8];
                #pragma unroll
                for (int qq = 0; qq < 8; qq++) {
                    int tg = tb + q8 * 8 + qq;
                    float v = (tg >= 0 && tg < Tn) ? __ldg(src + tg) : 0.f;
                    uint32_t hu, lu;
                    split_tf32(v, hu, lu);
                    hv[qq] = __uint_as_float(hu);
                    lv[qq] = __uint_as_float(lu);
                }
                int cb = (bseg * 32 + q8 * 8) ^ xk;
                *reinterpret_cast<float4*>(ph + cb)     = make_float4(hv[0], hv[1], hv[2], hv[3]);
                *reinterpret_cast<float4*>(ph + cb + 4) = make_float4(hv[4], hv[5], hv[6], hv[7]);
                *reinterpret_cast<float4*>(pl + cb)     = make_float4(lv[0], lv[1], lv[2], lv[3]);
                *reinterpret_cast<float4*>(pl + cb + 4) = make_float4(lv[4], lv[5], lv[6], lv[7]);
            }
        }

        asm volatile("cp.async.wait_group %0;" :: "n"(1) : "memory");
        if (c + 1 == NCHUNK)
            asm volatile("cp.async.wait_group 0;" ::: "memory");
        __syncthreads();   // S1: A(c), B(c) visible

        const float* Ah = sA + buf * 8192;          // [32][128]
        const float* Al = Ah + KC * 128;

        for (int ks = 0; ks < 4; ks++) {
            const int kb = ks * 8;
            // A fragments (conflict-free via xr swizzle)
            uint32_t aH[4][4], aL[4][4];
            #pragma unroll
            for (int mt = 0; mt < 4; mt++) {
                int col0 = (m0 + mt * 16 + g) ^ xr;
                int r0 = (kb + tig) * 128, r1 = (kb + tig + 4) * 128;
                aH[mt][0] = __float_as_uint(Ah[r0 + col0]);
                aH[mt][1] = __float_as_uint(Ah[r0 + (col0 ^ 8)]);
                aH[mt][2] = __float_as_uint(Ah[r1 + col0]);
                aH[mt][3] = __float_as_uint(Ah[r1 + (col0 ^ 8)]);
                aL[mt][0] = __float_as_uint(Al[r0 + col0]);
                aL[mt][1] = __float_as_uint(Al[r0 + (col0 ^ 8)]);
                aL[mt][2] = __float_as_uint(Al[r1 + col0]);
                aL[mt][3] = __float_as_uint(Al[r1 + (col0 ^ 8)]);
            }
            #pragma unroll
            for (int nt = 0; nt < 8; nt++) {
                int col = (n0 + nt * 8 + g) ^ xr;
                int r0 = (kb + tig) * 256, r1 = (kb + tig + 4) * 256;
                uint32_t b0h = __float_as_uint(sBh[r0 + col]);
                uint32_t b1h = __float_as_uint(sBh[r1 + col]);
                uint32_t b0l = __float_as_uint(sBl[r0 + col]);
                uint32_t b1l = __float_as_uint(sBl[r1 + col]);
                #pragma unroll
                for (int mt = 0; mt < 4; mt++) {
                    mma_tf32(acc[mt][nt], aH[mt], b0h, b1h);
                    mma_tf32(acc[mt][nt], aL[mt], b0h, b1h);
                    mma_tf32(acc[mt][nt], aH[mt], b0l, b1l);
                }
            }
        }
        __syncthreads();   // S2: MMAs retired before buffers overwritten
    }

    // Epilogue: D[o][t] -> out. c0,c1 = row g cols 2tig,2tig+1; c2,c3 = row g+8
    #pragma unroll
    for (int mt = 0; mt < 4; mt++) {
        int o = m0 + mt * 16 + g;
        float* row0 = out + (size_t)(b * Cn + o) * Tn + t0;
        float* row1 = row0 + 8 * Tn;
        #pragma unroll
        for (int nt = 0; nt < 8; nt++) {
            int tcol = n0 + nt * 8 + tig * 2;
            reinterpret_cast<float2*>(row0 + tcol)[0] =
                make_float2(acc[mt][nt][0], acc[mt][nt][1]);
            reinterpret_cast<float2*>(row1 + tcol)[0] =
                make_float2(acc[mt][nt][2], acc[mt][nt][3]);
        }
    }
}

// ---------------------------------------------------------------------------
extern "C" void kernel_launch(void* const* d_in, const int* in_sizes, int n_in,
                              void* d_out, int out_size) {
    const float* x    = (const float*)d_in[0];
    const int*   lens = (const int*)  d_in[1];
    const float* w1   = (const float*)d_in[2];
    const float* b1   = (const float*)d_in[3];
    const float* w2   = (const float*)d_in[4];
    float* out = (float*)d_out;

    cudaFuncSetAttribute(conv_kernel,
                         cudaFuncAttributeMaxDynamicSharedMemorySize, SMEM_BYTES);

    gap_kernel<<<Bn * Cn, 256>>>(x, lens);
    fc1_kernel<<<Bn, 256>>>(w1, b1);
    wd_kernel<<<(Bn * NCHUNK * KC * 128) / 256, 256>>>(w2);
    conv_kernel<<<dim3(NBLK, Bn), 256, SMEM_BYTES>>>(x, out);
}

// round 13
// speedup vs baseline: 1.3028x; 1.3028x over previous
#include <cuda_runtime.h>
#include <cstdint>

// Problem constants
#define Bn   32
#define Cn   128
#define Tn   8192
#define Kn   5
#define MCn  256
#define KTOT (Cn * Kn)        // 640
#define KC   32               // K per chunk
#define NCHUNK (KTOT / KC)    // 20
#define BT   128              // t per block tile
#define NBLK (Tn / BT)        // 64

// SMEM: A double buffer (hi+lo planes) 64KB @0 ; B hi 16KB @16384f ; B lo @20480f
#define SMEM_BYTES 98304

// Scratch
__device__ float g_gap[Bn * Cn];
__device__ float g_h[Bn * MCn];
// A tiles: [b][chunk][plane hi/lo][k(32)][o(128)] floats, o pre-XOR-swizzled
__device__ float g_wa[(size_t)Bn * NCHUNK * 2 * KC * 128];

// ---------------- helpers ----------------
__device__ __forceinline__ void split_tf32(float v, uint32_t& hi, uint32_t& lo) {
    uint32_t h;
    asm("cvt.rna.tf32.f32 %0, %1;" : "=r"(h) : "f"(v));
    float l = v - __uint_as_float(h);
    asm("cvt.rna.tf32.f32 %0, %1;" : "=r"(lo) : "f"(l));
    hi = h;
}
__device__ __forceinline__ void mma_tf32(float* d, const uint32_t a[4],
                                         uint32_t b0, uint32_t b1) {
    asm volatile(
        "mma.sync.aligned.m16n8k8.row.col.f32.tf32.tf32.f32 "
        "{%0,%1,%2,%3}, {%4,%5,%6,%7}, {%8,%9}, {%0,%1,%2,%3};"
        : "+f"(d[0]), "+f"(d[1]), "+f"(d[2]), "+f"(d[3])
        : "r"(a[0]), "r"(a[1]), "r"(a[2]), "r"(a[3]), "r"(b0), "r"(b1));
}

// ---------------------------------------------------------------------------
// Stage 1: masked global average pool.
// ---------------------------------------------------------------------------
__global__ void gap_kernel(const float* __restrict__ x, const int* __restrict__ lens) {
    int bc = blockIdx.x;
    const float4* row = reinterpret_cast<const float4*>(x + (size_t)bc * Tn);
    float s = 0.f;
    for (int i = threadIdx.x; i < Tn / 4; i += blockDim.x) {
        float4 v = row[i];
        s += (v.x + v.y) + (v.z + v.w);
    }
    for (int o = 16; o; o >>= 1) s += __shfl_down_sync(0xffffffffu, s, o);
    __shared__ float sm[8];
    int w = threadIdx.x >> 5, l = threadIdx.x & 31;
    if (l == 0) sm[w] = s;
    __syncthreads();
    if (threadIdx.x == 0) {
        float tot = 0.f;
        #pragma unroll
        for (int i = 0; i < 8; i++) tot += sm[i];
        g_gap[bc] = tot / (float)lens[bc / Cn];
    }
}

// ---------------------------------------------------------------------------
// Stage 2: h = sigmoid(gap @ w1^T + b1)
// ---------------------------------------------------------------------------
__global__ void fc1_kernel(const float* __restrict__ w1, const float* __restrict__ b1) {
    int b = blockIdx.x;
    __shared__ float sg[Cn];
    if (threadIdx.x < Cn) sg[threadIdx.x] = g_gap[b * Cn + threadIdx.x];
    __syncthreads();
    int j = threadIdx.x;
    const float* wr = w1 + (size_t)j * Cn;
    float z = b1[j];
    #pragma unroll 8
    for (int c = 0; c < Cn; c++) z += sg[c] * wr[c];
    g_h[b * MCn + j] = 1.f / (1.f + expf(-z));
}

// ---------------------------------------------------------------------------
// Stage 2.5: dynamic weights -> tf32 hi/lo planes, XOR-swizzled o index.
// ---------------------------------------------------------------------------
__global__ void wd_kernel(const float* __restrict__ w2) {
    int idx = blockIdx.x * 256 + threadIdx.x;
    int o = idx & 127;
    int r = idx >> 7;
    int k = r & 31; r >>= 5;
    int c = r % NCHUNK;
    int b = r / NCHUNK;
    int ik = c * KC + k;
    int i  = ik / 5;
    float v = w2[o * KTOT + ik] * g_h[b * MCn + 2 * o + (i >= 64 ? 1 : 0)];
    uint32_t hi, lo;
    split_tf32(v, hi, lo);
    int col = o ^ ((k & 3) << 3);
    float* base = g_wa + ((size_t)(b * NCHUNK + c) * 2) * (KC * 128);
    base[k * 128 + col]            = __uint_as_float(hi);
    base[KC * 128 + k * 128 + col] = __uint_as_float(lo);
}

// ---------------------------------------------------------------------------
// Stage 3: implicit-GEMM conv via mma.sync tf32 (3xTF32).
// Block: 128 o x 128 t, 8 warps of 64 o x 32 t, 2 blocks/SM.
// ---------------------------------------------------------------------------
__global__ void __launch_bounds__(256, 2)
conv_kernel(const float* __restrict__ x, float* __restrict__ out) {
    extern __shared__ __align__(16) float smem[];
    float* sA  = smem;               // [2 buf][2 planes][32][128]
    float* sBh = smem + 16384;       // [32][128]
    float* sBl = smem + 20480;       // [32][128]

    const int tid = threadIdx.x;
    const int t0 = blockIdx.x * BT;
    const int b  = blockIdx.y;
    const int w  = tid >> 5, lane = tid & 31;
    const int g  = lane >> 2, tig = lane & 3;
    const int m0 = (w & 1) * 64;
    const int n0 = (w >> 1) * 32;
    const uint32_t xr = (uint32_t)(tig << 3);

    const float* xb   = x + (size_t)b * Cn * Tn;
    const float* wa_b = g_wa + (size_t)b * NCHUNK * 2 * KC * 128;

    float acc[4][4][4];
    #pragma unroll
    for (int mt = 0; mt < 4; mt++)
        #pragma unroll
        for (int nt = 0; nt < 4; nt++)
            #pragma unroll
            for (int q = 0; q < 4; q++) acc[mt][nt][q] = 0.f;

    // B-build mapping: 32 k-rows x 8 segments of 16 t
    const int bks  = tid >> 3;
    const int bseg = tid & 7;

    // prefetch A chunk 0 (32KB = 2048 x float4)
    {
        const float4* src = reinterpret_cast<const float4*>(wa_b);
        #pragma unroll
        for (int e = 0; e < 8; e++) {
            uint32_t du;
            asm("{ .reg .u64 t; cvta.to.shared.u64 t, %1; cvt.u32.u64 %0, t; }"
                : "=r"(du) : "l"(sA + (e * 256 + tid) * 4));
            asm volatile("cp.async.cg.shared.global [%0], [%1], 16;"
                         :: "r"(du), "l"(src + e * 256 + tid) : "memory");
        }
        asm volatile("cp.async.commit_group;" ::: "memory");
    }

    for (int c = 0; c < NCHUNK; c++) {
        const int buf = c & 1;
        if (c + 1 < NCHUNK) {
            const float4* src = reinterpret_cast<const float4*>(
                wa_b + (size_t)(c + 1) * 2 * KC * 128);
            float* dst = sA + ((c + 1) & 1) * 8192;
            #pragma unroll
            for (int e = 0; e < 8; e++) {
                uint32_t du;
                asm("{ .reg .u64 t; cvta.to.shared.u64 t, %1; cvt.u32.u64 %0, t; }"
                    : "=r"(du) : "l"(dst + (e * 256 + tid) * 4));
                asm volatile("cp.async.cg.shared.global [%0], [%1], 16;"
                             :: "r"(du), "l"(src + e * 256 + tid) : "memory");
            }
            asm volatile("cp.async.commit_group;" ::: "memory");
        }

        // build B chunk: 32 k x 128 t, hi/lo planes, col = t ^ ((k&3)<<3)
        {
            int ik = c * KC + bks;
            int i  = ik / 5;
            int kk = ik - i * 5;
            const float* src = xb + (size_t)i * Tn;
            int tb = t0 + bseg * 16 + kk - 2;
            int xk = (bks & 3) << 3;
            float* ph = sBh + bks * 128;
            float* pl = sBl + bks * 128;
            #pragma unroll
            for (int q8 = 0; q8 < 2; q8++) {
                float hv[8], lv[8];
                #pragma unroll
                for (int qq = 0; qq < 8; qq++) {
                    int tg = tb + q8 * 8 + qq;
                    float v = (tg >= 0 && tg < Tn) ? __ldg(src + tg) : 0.f;
                    uint32_t hu, lu;
                    split_tf32(v, hu, lu);
                    hv[qq] = __uint_as_float(hu);
                    lv[qq] = __uint_as_float(lu);
                }
                int cb = (bseg * 16 + q8 * 8) ^ xk;
                *reinterpret_cast<float4*>(ph + cb)     = make_float4(hv[0], hv[1], hv[2], hv[3]);
                *reinterpret_cast<float4*>(ph + cb + 4) = make_float4(hv[4], hv[5], hv[6], hv[7]);
                *reinterpret_cast<float4*>(pl + cb)     = make_float4(lv[0], lv[1], lv[2], lv[3]);
                *reinterpret_cast<float4*>(pl + cb + 4) = make_float4(lv[4], lv[5], lv[6], lv[7]);
            }
        }

        asm volatile("cp.async.wait_group %0;" :: "n"(1) : "memory");
        if (c + 1 == NCHUNK)
            asm volatile("cp.async.wait_group 0;" ::: "memory");
        __syncthreads();

        const float* Ah = sA + buf * 8192;   // [32][128]
        const float* Al = Ah + KC * 128;

        #pragma unroll
        for (int ks = 0; ks < 4; ks++) {
            const int kb = ks * 8;
            const int r0 = (kb + tig) * 128, r1 = (kb + tig + 4) * 128;

            // ---- pass 1: aH * (bH + bL) ----
            {
                uint32_t aH[4][4];
                #pragma unroll
                for (int mt = 0; mt < 4; mt++) {
                    int col0 = (m0 + mt * 16 + g) ^ xr;
                    aH[mt][0] = __float_as_uint(Ah[r0 + col0]);
                    aH[mt][1] = __float_as_uint(Ah[r0 + (col0 ^ 8)]);
                    aH[mt][2] = __float_as_uint(Ah[r1 + col0]);
                    aH[mt][3] = __float_as_uint(Ah[r1 + (col0 ^ 8)]);
                }
                #pragma unroll
                for (int nt = 0; nt < 4; nt++) {
                    int col = (n0 + nt * 8 + g) ^ xr;
                    uint32_t b0h = __float_as_uint(sBh[r0 + col]);
                    uint32_t b1h = __float_as_uint(sBh[r1 + col]);
                    uint32_t b0l = __float_as_uint(sBl[r0 + col]);
                    uint32_t b1l = __float_as_uint(sBl[r1 + col]);
                    #pragma unroll
                    for (int mt = 0; mt < 4; mt++) {
                        mma_tf32(acc[mt][nt], aH[mt], b0h, b1h);
                        mma_tf32(acc[mt][nt], aH[mt], b0l, b1l);
                    }
                }
            }
            // ---- pass 2: aL * bH ----
            {
                uint32_t aL[4][4];
                #pragma unroll
                for (int mt = 0; mt < 4; mt++) {
                    int col0 = (m0 + mt * 16 + g) ^ xr;
                    aL[mt][0] = __float_as_uint(Al[r0 + col0]);
                    aL[mt][1] = __float_as_uint(Al[r0 + (col0 ^ 8)]);
                    aL[mt][2] = __float_as_uint(Al[r1 + col0]);
                    aL[mt][3] = __float_as_uint(Al[r1 + (col0 ^ 8)]);
                }
                #pragma unroll
                for (int nt = 0; nt < 4; nt++) {
                    int col = (n0 + nt * 8 + g) ^ xr;
                    uint32_t b0h = __float_as_uint(sBh[r0 + col]);
                    uint32_t b1h = __float_as_uint(sBh[r1 + col]);
                    #pragma unroll
                    for (int mt = 0; mt < 4; mt++)
                        mma_tf32(acc[mt][nt], aL[mt], b0h, b1h);
                }
            }
        }
        __syncthreads();
    }

    // Epilogue
    #pragma unroll
    for (int mt = 0; mt < 4; mt++) {
        int o = m0 + mt * 16 + g;
        float* row0 = out + (size_t)(b * Cn + o) * Tn + t0;
        float* row1 = row0 + 8 * Tn;
        #pragma unroll
        for (int nt = 0; nt < 4; nt++) {
            int tcol = n0 + nt * 8 + tig * 2;
            reinterpret_cast<float2*>(row0 + tcol)[0] =
                make_float2(acc[mt][nt][0], acc[mt][nt][1]);
            reinterpret_cast<float2*>(row1 + tcol)[0] =
                make_float2(acc[mt][nt][2], acc[mt][nt][3]);
        }
    }
}

// ---------------------------------------------------------------------------
extern "C" void kernel_launch(void* const* d_in, const int* in_sizes, int n_in,
                              void* d_out, int out_size) {
    const float* x    = (const float*)d_in[0];
    const int*   lens = (const int*)  d_in[1];
    const float* w1   = (const float*)d_in[2];
    const float* b1   = (const float*)d_in[3];
    const float* w2   = (const float*)d_in[4];
    float* out = (float*)d_out;

    cudaFuncSetAttribute(conv_kernel,
                         cudaFuncAttributeMaxDynamicSharedMemorySize, SMEM_BYTES);

    gap_kernel<<<Bn * Cn, 256>>>(x, lens);
    fc1_kernel<<<Bn, 256>>>(w1, b1);
    wd_kernel<<<(Bn * NCHUNK * KC * 128) / 256, 256>>>(w2);
    conv_kernel<<<dim3(NBLK, Bn), 256, SMEM_BYTES>>>(x, out);
}

// round 14
// speedup vs baseline: 1.8800x; 1.4430x over previous
#include <cuda_runtime.h>
#include <cstdint>

// Problem constants
#define Bn   32
#define Cn   128
#define Tn   8192
#define Kn   5
#define MCn  256
#define KTOT (Cn * Kn)        // 640
#define KC   32               // K per chunk
#define NCHUNK (KTOT / KC)    // 20
#define BT   128              // t per block tile
#define NBLK (Tn / BT)        // 64

// A tile: fragment-packed, 8192 floats (32KB) per chunk: [plane(2)][ks(4)][og(8)][lane(32)][q(4)]
#define ATILE 8192
// x panel: 8 rows x 136 cols, hi+lo planes
#define PRS   136
#define PPLANE (8 * PRS)          // 1088 floats
#define PBUF   (2 * PPLANE)       // 2176 floats per buffer
#define PANEL_OFF (2 * ATILE)     // float offset of panels in smem
#define SMEM_BYTES ((2 * ATILE + 2 * PBUF) * 4)   // 82944

// Scratch
__device__ float g_gap[Bn * Cn];
__device__ float g_h[Bn * MCn];
// A tiles: [b][chunk][ATILE] fragment-packed
__device__ float g_wa[(size_t)Bn * NCHUNK * ATILE];

// ---------------- helpers ----------------
__device__ __forceinline__ void split_tf32(float v, uint32_t& hi, uint32_t& lo) {
    uint32_t h;
    asm("cvt.rna.tf32.f32 %0, %1;" : "=r"(h) : "f"(v));
    float l = v - __uint_as_float(h);
    asm("cvt.rna.tf32.f32 %0, %1;" : "=r"(lo) : "f"(l));
    hi = h;
}
__device__ __forceinline__ void mma_tf32(float* d, const uint32_t a[4],
                                         uint32_t b0, uint32_t b1) {
    asm volatile(
        "mma.sync.aligned.m16n8k8.row.col.f32.tf32.tf32.f32 "
        "{%0,%1,%2,%3}, {%4,%5,%6,%7}, {%8,%9}, {%0,%1,%2,%3};"
        : "+f"(d[0]), "+f"(d[1]), "+f"(d[2]), "+f"(d[3])
        : "r"(a[0]), "r"(a[1]), "r"(a[2]), "r"(a[3]), "r"(b0), "r"(b1));
}

// ---------------------------------------------------------------------------
// Stage 1: masked global average pool.
// ---------------------------------------------------------------------------
__global__ void gap_kernel(const float* __restrict__ x, const int* __restrict__ lens) {
    int bc = blockIdx.x;
    const float4* row = reinterpret_cast<const float4*>(x + (size_t)bc * Tn);
    float s = 0.f;
    for (int i = threadIdx.x; i < Tn / 4; i += blockDim.x) {
        float4 v = row[i];
        s += (v.x + v.y) + (v.z + v.w);
    }
    for (int o = 16; o; o >>= 1) s += __shfl_down_sync(0xffffffffu, s, o);
    __shared__ float sm[8];
    int w = threadIdx.x >> 5, l = threadIdx.x & 31;
    if (l == 0) sm[w] = s;
    __syncthreads();
    if (threadIdx.x == 0) {
        float tot = 0.f;
        #pragma unroll
        for (int i = 0; i < 8; i++) tot += sm[i];
        g_gap[bc] = tot / (float)lens[bc / Cn];
    }
}

// ---------------------------------------------------------------------------
// Stage 2: h = sigmoid(gap @ w1^T + b1)
// ---------------------------------------------------------------------------
__global__ void fc1_kernel(const float* __restrict__ w1, const float* __restrict__ b1) {
    int b = blockIdx.x;
    __shared__ float sg[Cn];
    if (threadIdx.x < Cn) sg[threadIdx.x] = g_gap[b * Cn + threadIdx.x];
    __syncthreads();
    int j = threadIdx.x;
    const float* wr = w1 + (size_t)j * Cn;
    float z = b1[j];
    #pragma unroll 8
    for (int c = 0; c < Cn; c++) z += sg[c] * wr[c];
    g_h[b * MCn + j] = 1.f / (1.f + expf(-z));
}

// ---------------------------------------------------------------------------
// Stage 2.5: dynamic weights -> tf32 hi/lo, FRAGMENT-PACKED A tiles.
// One thread per (b,c,ks,og,lane): writes 4 hi + 4 lo floats (one frag each).
// Frag values (a0..a3) = W[o][kk], W[o+8][kk], W[o][kk+4], W[o+8][kk+4].
// ---------------------------------------------------------------------------
__global__ void wd_kernel(const float* __restrict__ w2) {
    int idx = blockIdx.x * 256 + threadIdx.x;   // Bn*NCHUNK*4*8*32 total
    int lane = idx & 31;
    int og   = (idx >> 5) & 7;
    int ks   = (idx >> 8) & 3;
    int r    = idx >> 10;
    int c    = r % NCHUNK;
    int b    = r / NCHUNK;
    int g = lane >> 2, tig = lane & 3;

    int o0 = og * 16 + g;
    int kk0 = ks * 8 + tig;
    float hv[4], lv[4];
    #pragma unroll
    for (int q = 0; q < 4; q++) {
        int o  = o0 + (q & 1) * 8;
        int kk = kk0 + (q >> 1) * 4;
        int ik = c * KC + kk;
        int i  = ik / 5;
        float v = w2[o * KTOT + ik] * g_h[b * MCn + 2 * o + (i >= 64 ? 1 : 0)];
        uint32_t hu, lu;
        split_tf32(v, hu, lu);
        hv[q] = __uint_as_float(hu);
        lv[q] = __uint_as_float(lu);
    }
    float* base = g_wa + (size_t)(b * NCHUNK + c) * ATILE;
    int offH = ((0 * 4 + ks) * 8 + og) * 128 + lane * 4;
    int offL = ((1 * 4 + ks) * 8 + og) * 128 + lane * 4;
    *reinterpret_cast<float4*>(base + offH) = make_float4(hv[0], hv[1], hv[2], hv[3]);
    *reinterpret_cast<float4*>(base + offL) = make_float4(lv[0], lv[1], lv[2], lv[3]);
}

// ---------------------------------------------------------------------------
// Stage 3: implicit-GEMM conv via mma.sync tf32 (3xTF32), x-panel B.
// Block: 128 o x 128 t, 8 warps of 64 o x 32 t, 2 blocks/SM, 1 sync/chunk.
// ---------------------------------------------------------------------------
__global__ void __launch_bounds__(256, 2)
conv_kernel(const float* __restrict__ x, float* __restrict__ out) {
    extern __shared__ __align__(16) float smem[];
    float* sA = smem;                    // [2 buf][ATILE]
    float* sP = smem + PANEL_OFF;        // [2 buf][hi 1088 | lo 1088]

    const int tid = threadIdx.x;
    const int t0 = blockIdx.x * BT;
    const int b  = blockIdx.y;
    const int w  = tid >> 5, lane = tid & 31;
    const int g  = lane >> 2, tig = lane & 3;
    const int m0 = (w & 1) * 64;
    const int og0 = m0 >> 4;             // 0 or 4
    const int n0 = (w >> 1) * 32;

    const float* xb   = x + (size_t)b * Cn * Tn;
    const float* wa_b = g_wa + (size_t)b * NCHUNK * ATILE;

    float acc[4][4][4];
    #pragma unroll
    for (int mt = 0; mt < 4; mt++)
        #pragma unroll
        for (int nt = 0; nt < 4; nt++)
            #pragma unroll
            for (int q = 0; q < 4; q++) acc[mt][nt][q] = 0.f;

    // ---- panel fill for chunk cc into buffer pb ----
    auto fill_panel = [&](int cc, int pb) {
        int i0 = (KC * cc) / 5;
        float* pH = sP + pb * PBUF;
        float* pL = pH + PPLANE;
        #pragma unroll
        for (int q = tid; q < 272; q += 256) {
            int row = q / 34;
            int col = (q - row * 34) * 4;
            int i = i0 + row;
            int t = t0 - 2 + col;
            float hv[4], lv[4];
            #pragma unroll
            for (int j = 0; j < 4; j++) {
                int tt = t + j;
                float v = (i < Cn && tt >= 0 && tt < Tn)
                          ? __ldg(xb + (size_t)i * Tn + tt) : 0.f;
                uint32_t hu, lu;
                split_tf32(v, hu, lu);
                hv[j] = __uint_as_float(hu);
                lv[j] = __uint_as_float(lu);
            }
            *reinterpret_cast<float4*>(pH + row * PRS + col) =
                make_float4(hv[0], hv[1], hv[2], hv[3]);
            *reinterpret_cast<float4*>(pL + row * PRS + col) =
                make_float4(lv[0], lv[1], lv[2], lv[3]);
        }
    };
    auto prefetch_A = [&](int cc, int ab) {
        const float4* src = reinterpret_cast<const float4*>(wa_b + (size_t)cc * ATILE);
        float* dst = sA + ab * ATILE;
        #pragma unroll
        for (int e = 0; e < 8; e++) {
            uint32_t du;
            asm("{ .reg .u64 t; cvta.to.shared.u64 t, %1; cvt.u32.u64 %0, t; }"
                : "=r"(du) : "l"(dst + (e * 256 + tid) * 4));
            asm volatile("cp.async.cg.shared.global [%0], [%1], 16;"
                         :: "r"(du), "l"(src + e * 256 + tid) : "memory");
        }
        asm volatile("cp.async.commit_group;" ::: "memory");
    };

    // prologue
    prefetch_A(0, 0);
    fill_panel(0, 0);

    for (int c = 0; c < NCHUNK; c++) {
        const int buf = c & 1;
        asm volatile("cp.async.wait_group 0;" ::: "memory");
        __syncthreads();   // A(c)+panel(c) visible; MMA(c-1) reads retired

        if (c + 1 < NCHUNK) {
            prefetch_A(c + 1, buf ^ 1);
            fill_panel(c + 1, buf ^ 1);
        }

        const float* Ab = sA + buf * ATILE;
        const float* pH = sP + buf * PBUF;
        const float* pL = pH + PPLANE;
        const int i0 = (KC * c) / 5;

        #pragma unroll
        for (int ks = 0; ks < 4; ks++) {
            // per-thread B addresses for this ks
            int ik0 = c * KC + ks * 8 + tig;
            int ik1 = ik0 + 4;
            int ia = ik0 / 5, ka = ik0 - ia * 5;
            int ib = ik1 / 5, kb2 = ik1 - ib * 5;
            int offB0 = (ia - i0) * PRS + ka + n0 + g;
            int offB1 = (ib - i0) * PRS + kb2 + n0 + g;

            // ---- pass 1: aH * (bH + bL) ----
            {
                uint32_t aH[4][4];
                #pragma unroll
                for (int mt = 0; mt < 4; mt++) {
                    float4 fa = *reinterpret_cast<const float4*>(
                        Ab + ((0 * 4 + ks) * 8 + og0 + mt) * 128 + lane * 4);
                    aH[mt][0] = __float_as_uint(fa.x);
                    aH[mt][1] = __float_as_uint(fa.y);
                    aH[mt][2] = __float_as_uint(fa.z);
                    aH[mt][3] = __float_as_uint(fa.w);
                }
                #pragma unroll
                for (int nt = 0; nt < 4; nt++) {
                    uint32_t b0h = __float_as_uint(pH[offB0 + nt * 8]);
                    uint32_t b1h = __float_as_uint(pH[offB1 + nt * 8]);
                    uint32_t b0l = __float_as_uint(pL[offB0 + nt * 8]);
                    uint32_t b1l = __float_as_uint(pL[offB1 + nt * 8]);
                    #pragma unroll
                    for (int mt = 0; mt < 4; mt++) {
                        mma_tf32(acc[mt][nt], aH[mt], b0h, b1h);
                        mma_tf32(acc[mt][nt], aH[mt], b0l, b1l);
                    }
                }
            }
            // ---- pass 2: aL * bH ----
            {
                uint32_t aL[4][4];
                #pragma unroll
                for (int mt = 0; mt < 4; mt++) {
                    float4 fa = *reinterpret_cast<const float4*>(
                        Ab + ((1 * 4 + ks) * 8 + og0 + mt) * 128 + lane * 4);
                    aL[mt][0] = __float_as_uint(fa.x);
                    aL[mt][1] = __float_as_uint(fa.y);
                    aL[mt][2] = __float_as_uint(fa.z);
                    aL[mt][3] = __float_as_uint(fa.w);
                }
                #pragma unroll
                for (int nt = 0; nt < 4; nt++) {
                    uint32_t b0h = __float_as_uint(pH[offB0 + nt * 8]);
                    uint32_t b1h = __float_as_uint(pH[offB1 + nt * 8]);
                    #pragma unroll
                    for (int mt = 0; mt < 4; mt++)
                        mma_tf32(acc[mt][nt], aL[mt], b0h, b1h);
                }
            }
        }
    }

    // Epilogue (unchanged mapping from R13)
    #pragma unroll
    for (int mt = 0; mt < 4; mt++) {
        int o = m0 + mt * 16 + g;
        float* row0 = out + (size_t)(b * Cn + o) * Tn + t0;
        float* row1 = row0 + 8 * Tn;
        #pragma unroll
        for (int nt = 0; nt < 4; nt++) {
            int tcol = n0 + nt * 8 + tig * 2;
            reinterpret_cast<float2*>(row0 + tcol)[0] =
                make_float2(acc[mt][nt][0], acc[mt][nt][1]);
            reinterpret_cast<float2*>(row1 + tcol)[0] =
                make_float2(acc[mt][nt][2], acc[mt][nt][3]);
        }
    }
}

// ---------------------------------------------------------------------------
extern "C" void kernel_launch(void* const* d_in, const int* in_sizes, int n_in,
                              void* d_out, int out_size) {
    const float* x    = (const float*)d_in[0];
    const int*   lens = (const int*)  d_in[1];
    const float* w1   = (const float*)d_in[2];
    const float* b1   = (const float*)d_in[3];
    const float* w2   = (const float*)d_in[4];
    float* out = (float*)d_out;

    cudaFuncSetAttribute(conv_kernel,
                         cudaFuncAttributeMaxDynamicSharedMemorySize, SMEM_BYTES);

    gap_kernel<<<Bn * Cn, 256>>>(x, lens);
    fc1_kernel<<<Bn, 256>>>(w1, b1);
    wd_kernel<<<(Bn * NCHUNK * 4 * 8 * 32) / 256, 256>>>(w2);
    conv_kernel<<<dim3(NBLK, Bn), 256, SMEM_BYTES>>>(x, out);
}

// round 15
// speedup vs baseline: 2.4182x; 1.2863x over previous
#include <cuda_runtime.h>
#include <cstdint>

// Problem constants
#define Bn   32
#define Cn   128
#define Tn   8192
#define Kn   5
#define MCn  256
#define KTOT (Cn * Kn)        // 640
#define KC   32               // K per chunk
#define NCHUNK (KTOT / KC)    // 20
#define BT   128              // t per block tile
#define NBLK (Tn / BT)        // 64

// A tile: fragment-packed HI ONLY, 4096 floats (16KB): [ks(4)][og(8)][lane(32)][q(4)]
#define ATILE 4096
// x panel: 8 rows x 136 cols, hi+lo planes
#define PRS   136
#define PPLANE (8 * PRS)          // 1088 floats
#define PBUF   (2 * PPLANE)       // 2176 floats per buffer
#define PANEL_OFF (2 * ATILE)     // float offset of panels in smem
#define SMEM_BYTES ((2 * ATILE + 2 * PBUF) * 4)   // 50176

// Scratch
__device__ float g_gap[Bn * Cn];
__device__ float g_h[Bn * MCn];
// A tiles: [b][chunk][ATILE] fragment-packed (hi plane only)
__device__ float g_wa[(size_t)Bn * NCHUNK * ATILE];

// ---------------- helpers ----------------
__device__ __forceinline__ void split_tf32(float v, uint32_t& hi, uint32_t& lo) {
    uint32_t h;
    asm("cvt.rna.tf32.f32 %0, %1;" : "=r"(h) : "f"(v));
    float l = v - __uint_as_float(h);
    asm("cvt.rna.tf32.f32 %0, %1;" : "=r"(lo) : "f"(l));
    hi = h;
}
__device__ __forceinline__ uint32_t tf32_of(float v) {
    uint32_t h;
    asm("cvt.rna.tf32.f32 %0, %1;" : "=r"(h) : "f"(v));
    return h;
}
__device__ __forceinline__ void mma_tf32(float* d, const uint32_t a[4],
                                         uint32_t b0, uint32_t b1) {
    asm volatile(
        "mma.sync.aligned.m16n8k8.row.col.f32.tf32.tf32.f32 "
        "{%0,%1,%2,%3}, {%4,%5,%6,%7}, {%8,%9}, {%0,%1,%2,%3};"
        : "+f"(d[0]), "+f"(d[1]), "+f"(d[2]), "+f"(d[3])
        : "r"(a[0]), "r"(a[1]), "r"(a[2]), "r"(a[3]), "r"(b0), "r"(b1));
}

// ---------------------------------------------------------------------------
// Stage 1: masked global average pool.
// ---------------------------------------------------------------------------
__global__ void gap_kernel(const float* __restrict__ x, const int* __restrict__ lens) {
    int bc = blockIdx.x;
    const float4* row = reinterpret_cast<const float4*>(x + (size_t)bc * Tn);
    float s = 0.f;
    for (int i = threadIdx.x; i < Tn / 4; i += blockDim.x) {
        float4 v = row[i];
        s += (v.x + v.y) + (v.z + v.w);
    }
    for (int o = 16; o; o >>= 1) s += __shfl_down_sync(0xffffffffu, s, o);
    __shared__ float sm[8];
    int w = threadIdx.x >> 5, l = threadIdx.x & 31;
    if (l == 0) sm[w] = s;
    __syncthreads();
    if (threadIdx.x == 0) {
        float tot = 0.f;
        #pragma unroll
        for (int i = 0; i < 8; i++) tot += sm[i];
        g_gap[bc] = tot / (float)lens[bc / Cn];
    }
}

// ---------------------------------------------------------------------------
// Stage 2: h = sigmoid(gap @ w1^T + b1)
// ---------------------------------------------------------------------------
__global__ void fc1_kernel(const float* __restrict__ w1, const float* __restrict__ b1) {
    int b = blockIdx.x;
    __shared__ float sg[Cn];
    if (threadIdx.x < Cn) sg[threadIdx.x] = g_gap[b * Cn + threadIdx.x];
    __syncthreads();
    int j = threadIdx.x;
    const float* wr = w1 + (size_t)j * Cn;
    float z = b1[j];
    #pragma unroll 8
    for (int c = 0; c < Cn; c++) z += sg[c] * wr[c];
    g_h[b * MCn + j] = 1.f / (1.f + expf(-z));
}

// ---------------------------------------------------------------------------
// Stage 2.5: dynamic weights -> tf32 hi, FRAGMENT-PACKED A tiles (hi only).
// One thread per (b,c,ks,og,lane): writes one 4-float fragment.
// Frag values (a0..a3) = W[o][kk], W[o+8][kk], W[o][kk+4], W[o+8][kk+4].
// ---------------------------------------------------------------------------
__global__ void wd_kernel(const float* __restrict__ w2) {
    int idx = blockIdx.x * 256 + threadIdx.x;   // Bn*NCHUNK*4*8*32 total
    int lane = idx & 31;
    int og   = (idx >> 5) & 7;
    int ks   = (idx >> 8) & 3;
    int r    = idx >> 10;
    int c    = r % NCHUNK;
    int b    = r / NCHUNK;
    int g = lane >> 2, tig = lane & 3;

    int o0 = og * 16 + g;
    int kk0 = ks * 8 + tig;
    float hv[4];
    #pragma unroll
    for (int q = 0; q < 4; q++) {
        int o  = o0 + (q & 1) * 8;
        int kk = kk0 + (q >> 1) * 4;
        int ik = c * KC + kk;
        int i  = ik / 5;
        float v = w2[o * KTOT + ik] * g_h[b * MCn + 2 * o + (i >= 64 ? 1 : 0)];
        hv[q] = __uint_as_float(tf32_of(v));
    }
    float* base = g_wa + (size_t)(b * NCHUNK + c) * ATILE;
    int off = (ks * 8 + og) * 128 + lane * 4;
    *reinterpret_cast<float4*>(base + off) = make_float4(hv[0], hv[1], hv[2], hv[3]);
}

// ---------------------------------------------------------------------------
// Stage 3: implicit-GEMM conv via mma.sync tf32, 2-plane split aH*(bH+bL).
// Block: 128 o x 128 t, 8 warps of 64 o x 32 t, 2 blocks/SM, 1 sync/chunk.
// ---------------------------------------------------------------------------
__global__ void __launch_bounds__(256, 2)
conv_kernel(const float* __restrict__ x, float* __restrict__ out) {
    extern __shared__ __align__(16) float smem[];
    float* sA = smem;                    // [2 buf][ATILE]
    float* sP = smem + PANEL_OFF;        // [2 buf][hi 1088 | lo 1088]

    const int tid = threadIdx.x;
    const int t0 = blockIdx.x * BT;
    const int b  = blockIdx.y;
    const int w  = tid >> 5, lane = tid & 31;
    const int g  = lane >> 2, tig = lane & 3;
    const int m0 = (w & 1) * 64;
    const int og0 = m0 >> 4;             // 0 or 4
    const int n0 = (w >> 1) * 32;

    const float* xb   = x + (size_t)b * Cn * Tn;
    const float* wa_b = g_wa + (size_t)b * NCHUNK * ATILE;

    float acc[4][4][4];
    #pragma unroll
    for (int mt = 0; mt < 4; mt++)
        #pragma unroll
        for (int nt = 0; nt < 4; nt++)
            #pragma unroll
            for (int q = 0; q < 4; q++) acc[mt][nt][q] = 0.f;

    // ---- panel fill for chunk cc into buffer pb ----
    auto fill_panel = [&](int cc, int pb) {
        int i0 = (KC * cc) / 5;
        float* pH = sP + pb * PBUF;
        float* pL = pH + PPLANE;
        #pragma unroll
        for (int q = tid; q < 272; q += 256) {
            int row = q / 34;
            int col = (q - row * 34) * 4;
            int i = i0 + row;
            int t = t0 - 2 + col;
            float hv[4], lv[4];
            #pragma unroll
            for (int j = 0; j < 4; j++) {
                int tt = t + j;
                float v = (i < Cn && tt >= 0 && tt < Tn)
                          ? __ldg(xb + (size_t)i * Tn + tt) : 0.f;
                uint32_t hu, lu;
                split_tf32(v, hu, lu);
                hv[j] = __uint_as_float(hu);
                lv[j] = __uint_as_float(lu);
            }
            *reinterpret_cast<float4*>(pH + row * PRS + col) =
                make_float4(hv[0], hv[1], hv[2], hv[3]);
            *reinterpret_cast<float4*>(pL + row * PRS + col) =
                make_float4(lv[0], lv[1], lv[2], lv[3]);
        }
    };
    auto prefetch_A = [&](int cc, int ab) {
        const float4* src = reinterpret_cast<const float4*>(wa_b + (size_t)cc * ATILE);
        float* dst = sA + ab * ATILE;
        #pragma unroll
        for (int e = 0; e < 4; e++) {
            uint32_t du;
            asm("{ .reg .u64 t; cvta.to.shared.u64 t, %1; cvt.u32.u64 %0, t; }"
                : "=r"(du) : "l"(dst + (e * 256 + tid) * 4));
            asm volatile("cp.async.cg.shared.global [%0], [%1], 16;"
                         :: "r"(du), "l"(src + e * 256 + tid) : "memory");
        }
        asm volatile("cp.async.commit_group;" ::: "memory");
    };

    // prologue
    prefetch_A(0, 0);
    fill_panel(0, 0);

    for (int c = 0; c < NCHUNK; c++) {
        const int buf = c & 1;
        asm volatile("cp.async.wait_group 0;" ::: "memory");
        __syncthreads();   // A(c)+panel(c) visible; MMA(c-1) reads retired

        if (c + 1 < NCHUNK) {
            prefetch_A(c + 1, buf ^ 1);
            fill_panel(c + 1, buf ^ 1);
        }

        const float* Ab = sA + buf * ATILE;
        const float* pH = sP + buf * PBUF;
        const float* pL = pH + PPLANE;
        const int i0 = (KC * c) / 5;

        #pragma unroll
        for (int ks = 0; ks < 4; ks++) {
            // per-thread B addresses for this ks
            int ik0 = c * KC + ks * 8 + tig;
            int ik1 = ik0 + 4;
            int ia = ik0 / 5, ka = ik0 - ia * 5;
            int ib = ik1 / 5, kb2 = ik1 - ib * 5;
            int offB0 = (ia - i0) * PRS + ka + n0 + g;
            int offB1 = (ib - i0) * PRS + kb2 + n0 + g;

            uint32_t aH[4][4];
            #pragma unroll
            for (int mt = 0; mt < 4; mt++) {
                float4 fa = *reinterpret_cast<const float4*>(
                    Ab + (ks * 8 + og0 + mt) * 128 + lane * 4);
                aH[mt][0] = __float_as_uint(fa.x);
                aH[mt][1] = __float_as_uint(fa.y);
                aH[mt][2] = __float_as_uint(fa.z);
                aH[mt][3] = __float_as_uint(fa.w);
            }
            #pragma unroll
            for (int nt = 0; nt < 4; nt++) {
                uint32_t b0h = __float_as_uint(pH[offB0 + nt * 8]);
                uint32_t b1h = __float_as_uint(pH[offB1 + nt * 8]);
                uint32_t b0l = __float_as_uint(pL[offB0 + nt * 8]);
                uint32_t b1l = __float_as_uint(pL[offB1 + nt * 8]);
                #pragma unroll
                for (int mt = 0; mt < 4; mt++) {
                    mma_tf32(acc[mt][nt], aH[mt], b0h, b1h);
                    mma_tf32(acc[mt][nt], aH[mt], b0l, b1l);
                }
            }
        }
    }

    // Epilogue
    #pragma unroll
    for (int mt = 0; mt < 4; mt++) {
        int o = m0 + mt * 16 + g;
        float* row0 = out + (size_t)(b * Cn + o) * Tn + t0;
        float* row1 = row0 + 8 * Tn;
        #pragma unroll
        for (int nt = 0; nt < 4; nt++) {
            int tcol = n0 + nt * 8 + tig * 2;
            reinterpret_cast<float2*>(row0 + tcol)[0] =
                make_float2(acc[mt][nt][0], acc[mt][nt][1]);
            reinterpret_cast<float2*>(row1 + tcol)[0] =
                make_float2(acc[mt][nt][2], acc[mt][nt][3]);
        }
    }
}

// ---------------------------------------------------------------------------
extern "C" void kernel_launch(void* const* d_in, const int* in_sizes, int n_in,
                              void* d_out, int out_size) {
    const float* x    = (const float*)d_in[0];
    const int*   lens = (const int*)  d_in[1];
    const float* w1   = (const float*)d_in[2];
    const float* b1   = (const float*)d_in[3];
    const float* w2   = (const float*)d_in[4];
    float* out = (float*)d_out;

    cudaFuncSetAttribute(conv_kernel,
                         cudaFuncAttributeMaxDynamicSharedMemorySize, SMEM_BYTES);

    gap_kernel<<<Bn * Cn, 256>>>(x, lens);
    fc1_kernel<<<Bn, 256>>>(w1, b1);
    wd_kernel<<<(Bn * NCHUNK * 4 * 8 * 32) / 256, 256>>>(w2);
    conv_kernel<<<dim3(NBLK, Bn), 256, SMEM_BYTES>>>(x, out);
}

// round 16
// speedup vs baseline: 3.5847x; 1.4824x over previous
#include <cuda_runtime.h>
#include <cstdint>

// Problem constants
#define Bn   32
#define Cn   128
#define Tn   8192
#define Kn   5
#define MCn  256
#define KTOT (Cn * Kn)        // 640
#define KC   32               // K per chunk
#define NCHUNK (KTOT / KC)    // 20
#define BT   128              // t per block tile
#define NBLK (Tn / BT)        // 64

// A tile: fragment-packed HI ONLY, 4096 floats (16KB): [ks(4)][og(8)][lane(32)][q(4)]
#define ATILE 4096
// x panel: 8 rows x 136 cols, hi plane only
#define PRS   136
#define PPLANE (8 * PRS)          // 1088 floats
#define PANEL_OFF (2 * ATILE)     // float offset of panels in smem
#define SMEM_BYTES ((2 * ATILE + 2 * PPLANE) * 4)   // 41472

// Scratch
__device__ float g_gap[Bn * Cn];
__device__ float g_h[Bn * MCn];
// A tiles: [b][chunk][ATILE] fragment-packed (hi plane only)
__device__ float g_wa[(size_t)Bn * NCHUNK * ATILE];

// ---------------- helpers ----------------
__device__ __forceinline__ uint32_t tf32_of(float v) {
    uint32_t h;
    asm("cvt.rna.tf32.f32 %0, %1;" : "=r"(h) : "f"(v));
    return h;
}
__device__ __forceinline__ void mma_tf32(float* d, const uint32_t a[4],
                                         uint32_t b0, uint32_t b1) {
    asm volatile(
        "mma.sync.aligned.m16n8k8.row.col.f32.tf32.tf32.f32 "
        "{%0,%1,%2,%3}, {%4,%5,%6,%7}, {%8,%9}, {%0,%1,%2,%3};"
        : "+f"(d[0]), "+f"(d[1]), "+f"(d[2]), "+f"(d[3])
        : "r"(a[0]), "r"(a[1]), "r"(a[2]), "r"(a[3]), "r"(b0), "r"(b1));
}

// ---------------------------------------------------------------------------
// Stage 1: masked global average pool.
// ---------------------------------------------------------------------------
__global__ void gap_kernel(const float* __restrict__ x, const int* __restrict__ lens) {
    int bc = blockIdx.x;
    const float4* row = reinterpret_cast<const float4*>(x + (size_t)bc * Tn);
    float s = 0.f;
    for (int i = threadIdx.x; i < Tn / 4; i += blockDim.x) {
        float4 v = row[i];
        s += (v.x + v.y) + (v.z + v.w);
    }
    for (int o = 16; o; o >>= 1) s += __shfl_down_sync(0xffffffffu, s, o);
    __shared__ float sm[8];
    int w = threadIdx.x >> 5, l = threadIdx.x & 31;
    if (l == 0) sm[w] = s;
    __syncthreads();
    if (threadIdx.x == 0) {
        float tot = 0.f;
        #pragma unroll
        for (int i = 0; i < 8; i++) tot += sm[i];
        g_gap[bc] = tot / (float)lens[bc / Cn];
    }
}

// ---------------------------------------------------------------------------
// Stage 2: h = sigmoid(gap @ w1^T + b1)
// ---------------------------------------------------------------------------
__global__ void fc1_kernel(const float* __restrict__ w1, const float* __restrict__ b1) {
    int b = blockIdx.x;
    __shared__ float sg[Cn];
    if (threadIdx.x < Cn) sg[threadIdx.x] = g_gap[b * Cn + threadIdx.x];
    __syncthreads();
    int j = threadIdx.x;
    const float* wr = w1 + (size_t)j * Cn;
    float z = b1[j];
    #pragma unroll 8
    for (int c = 0; c < Cn; c++) z += sg[c] * wr[c];
    g_h[b * MCn + j] = 1.f / (1.f + expf(-z));
}

// ---------------------------------------------------------------------------
// Stage 2.5: dynamic weights -> tf32 hi, FRAGMENT-PACKED A tiles (hi only).
// Frag values (a0..a3) = W[o][kk], W[o+8][kk], W[o][kk+4], W[o+8][kk+4].
// ---------------------------------------------------------------------------
__global__ void wd_kernel(const float* __restrict__ w2) {
    int idx = blockIdx.x * 256 + threadIdx.x;   // Bn*NCHUNK*4*8*32 total
    int lane = idx & 31;
    int og   = (idx >> 5) & 7;
    int ks   = (idx >> 8) & 3;
    int r    = idx >> 10;
    int c    = r % NCHUNK;
    int b    = r / NCHUNK;
    int g = lane >> 2, tig = lane & 3;

    int o0 = og * 16 + g;
    int kk0 = ks * 8 + tig;
    float hv[4];
    #pragma unroll
    for (int q = 0; q < 4; q++) {
        int o  = o0 + (q & 1) * 8;
        int kk = kk0 + (q >> 1) * 4;
        int ik = c * KC + kk;
        int i  = ik / 5;
        float v = w2[o * KTOT + ik] * g_h[b * MCn + 2 * o + (i >= 64 ? 1 : 0)];
        hv[q] = __uint_as_float(tf32_of(v));
    }
    float* base = g_wa + (size_t)(b * NCHUNK + c) * ATILE;
    int off = (ks * 8 + og) * 128 + lane * 4;
    *reinterpret_cast<float4*>(base + off) = make_float4(hv[0], hv[1], hv[2], hv[3]);
}

// ---------------------------------------------------------------------------
// Stage 3: implicit-GEMM conv via mma.sync tf32, single plane aH*bH.
// Block: 128 o x 128 t, 8 warps of 64 o x 32 t, 2 blocks/SM, 1 sync/chunk.
// ---------------------------------------------------------------------------
__global__ void __launch_bounds__(256, 2)
conv_kernel(const float* __restrict__ x, float* __restrict__ out) {
    extern __shared__ __align__(16) float smem[];
    float* sA = smem;                    // [2 buf][ATILE]
    float* sP = smem + PANEL_OFF;        // [2 buf][PPLANE]

    const int tid = threadIdx.x;
    const int t0 = blockIdx.x * BT;
    const int b  = blockIdx.y;
    const int w  = tid >> 5, lane = tid & 31;
    const int g  = lane >> 2, tig = lane & 3;
    const int m0 = (w & 1) * 64;
    const int og0 = m0 >> 4;             // 0 or 4
    const int n0 = (w >> 1) * 32;

    const float* xb   = x + (size_t)b * Cn * Tn;
    const float* wa_b = g_wa + (size_t)b * NCHUNK * ATILE;

    float acc[4][4][4];
    #pragma unroll
    for (int mt = 0; mt < 4; mt++)
        #pragma unroll
        for (int nt = 0; nt < 4; nt++)
            #pragma unroll
            for (int q = 0; q < 4; q++) acc[mt][nt][q] = 0.f;

    // ---- panel fill (hi only) for chunk cc into buffer pb ----
    auto fill_panel = [&](int cc, int pb) {
        int i0 = (KC * cc) / 5;
        float* pH = sP + pb * PPLANE;
        #pragma unroll
        for (int q = tid; q < 272; q += 256) {
            int row = q / 34;
            int col = (q - row * 34) * 4;
            int i = i0 + row;
            int t = t0 - 2 + col;
            float hv[4];
            #pragma unroll
            for (int j = 0; j < 4; j++) {
                int tt = t + j;
                float v = (i < Cn && tt >= 0 && tt < Tn)
                          ? __ldg(xb + (size_t)i * Tn + tt) : 0.f;
                hv[j] = __uint_as_float(tf32_of(v));
            }
            *reinterpret_cast<float4*>(pH + row * PRS + col) =
                make_float4(hv[0], hv[1], hv[2], hv[3]);
        }
    };
    auto prefetch_A = [&](int cc, int ab) {
        const float4* src = reinterpret_cast<const float4*>(wa_b + (size_t)cc * ATILE);
        float* dst = sA + ab * ATILE;
        #pragma unroll
        for (int e = 0; e < 4; e++) {
            uint32_t du;
            asm("{ .reg .u64 t; cvta.to.shared.u64 t, %1; cvt.u32.u64 %0, t; }"
                : "=r"(du) : "l"(dst + (e * 256 + tid) * 4));
            asm volatile("cp.async.cg.shared.global [%0], [%1], 16;"
                         :: "r"(du), "l"(src + e * 256 + tid) : "memory");
        }
        asm volatile("cp.async.commit_group;" ::: "memory");
    };

    // prologue
    prefetch_A(0, 0);
    fill_panel(0, 0);

    for (int c = 0; c < NCHUNK; c++) {
        const int buf = c & 1;
        asm volatile("cp.async.wait_group 0;" ::: "memory");
        __syncthreads();   // A(c)+panel(c) visible; MMA(c-1) reads retired

        if (c + 1 < NCHUNK) {
            prefetch_A(c + 1, buf ^ 1);
            fill_panel(c + 1, buf ^ 1);
        }

        const float* Ab = sA + buf * ATILE;
        const float* pH = sP + buf * PPLANE;
        const int i0 = (KC * c) / 5;

        #pragma unroll
        for (int ks = 0; ks < 4; ks++) {
            // per-thread B addresses for this ks
            int ik0 = c * KC + ks * 8 + tig;
            int ik1 = ik0 + 4;
            int ia = ik0 / 5, ka = ik0 - ia * 5;
            int ib = ik1 / 5, kb2 = ik1 - ib * 5;
            int offB0 = (ia - i0) * PRS + ka + n0 + g;
            int offB1 = (ib - i0) * PRS + kb2 + n0 + g;

            uint32_t aH[4][4];
            #pragma unroll
            for (int mt = 0; mt < 4; mt++) {
                float4 fa = *reinterpret_cast<const float4*>(
                    Ab + (ks * 8 + og0 + mt) * 128 + lane * 4);
                aH[mt][0] = __float_as_uint(fa.x);
                aH[mt][1] = __float_as_uint(fa.y);
                aH[mt][2] = __float_as_uint(fa.z);
                aH[mt][3] = __float_as_uint(fa.w);
            }
            #pragma unroll
            for (int nt = 0; nt < 4; nt++) {
                uint32_t b0h = __float_as_uint(pH[offB0 + nt * 8]);
                uint32_t b1h = __float_as_uint(pH[offB1 + nt * 8]);
                #pragma unroll
                for (int mt = 0; mt < 4; mt++)
                    mma_tf32(acc[mt][nt], aH[mt], b0h, b1h);
            }
        }
    }

    // Epilogue
    #pragma unroll
    for (int mt = 0; mt < 4; mt++) {
        int o = m0 + mt * 16 + g;
        float* row0 = out + (size_t)(b * Cn + o) * Tn + t0;
        float* row1 = row0 + 8 * Tn;
        #pragma unroll
        for (int nt = 0; nt < 4; nt++) {
            int tcol = n0 + nt * 8 + tig * 2;
            reinterpret_cast<float2*>(row0 + tcol)[0] =
                make_float2(acc[mt][nt][0], acc[mt][nt][1]);
            reinterpret_cast<float2*>(row1 + tcol)[0] =
                make_float2(acc[mt][nt][2], acc[mt][nt][3]);
        }
    }
}

// ---------------------------------------------------------------------------
extern "C" void kernel_launch(void* const* d_in, const int* in_sizes, int n_in,
                              void* d_out, int out_size) {
    const float* x    = (const float*)d_in[0];
    const int*   lens = (const int*)  d_in[1];
    const float* w1   = (const float*)d_in[2];
    const float* b1   = (const float*)d_in[3];
    const float* w2   = (const float*)d_in[4];
    float* out = (float*)d_out;

    cudaFuncSetAttribute(conv_kernel,
                         cudaFuncAttributeMaxDynamicSharedMemorySize, SMEM_BYTES);

    gap_kernel<<<Bn * Cn, 256>>>(x, lens);
    fc1_kernel<<<Bn, 256>>>(w1, b1);
    wd_kernel<<<(Bn * NCHUNK * 4 * 8 * 32) / 256, 256>>>(w2);
    conv_kernel<<<dim3(NBLK, Bn), 256, SMEM_BYTES>>>(x, out);
}

// round 17
// speedup vs baseline: 3.7033x; 1.0331x over previous
#include <cuda_runtime.h>
#include <cstdint>

// Problem constants
#define Bn   32
#define Cn   128
#define Tn   8192
#define Kn   5
#define MCn  256
#define KTOT (Cn * Kn)        // 640
#define KC   32               // K per chunk
#define NCHUNK (KTOT / KC)    // 20
#define BT   256              // t per block tile
#define NBLK (Tn / BT)        // 32

// A tile: fragment-packed HI ONLY, 4096 floats (16KB): [ks(4)][og(8)][lane(32)][q(4)]
#define ATILE 4096
// x panel: 8 rows x 264 cols (t0-4 .. t0+260), RAW fp32 (HW-truncated tf32)
#define PRS   264
#define PPLANE (8 * PRS)          // 2112 floats
#define PANEL_OFF (2 * ATILE)
#define SMEM_BYTES ((2 * ATILE + 2 * PPLANE) * 4)   // 49664

// Scratch
__device__ float g_gap[Bn * Cn];
__device__ float g_h[Bn * MCn];
// A tiles: [b][chunk][ATILE] fragment-packed (hi plane only)
__device__ float g_wa[(size_t)Bn * NCHUNK * ATILE];

// ---------------- helpers ----------------
__device__ __forceinline__ uint32_t tf32_of(float v) {
    uint32_t h;
    asm("cvt.rna.tf32.f32 %0, %1;" : "=r"(h) : "f"(v));
    return h;
}
__device__ __forceinline__ void mma_tf32(float* d, const uint32_t a[4],
                                         uint32_t b0, uint32_t b1) {
    asm volatile(
        "mma.sync.aligned.m16n8k8.row.col.f32.tf32.tf32.f32 "
        "{%0,%1,%2,%3}, {%4,%5,%6,%7}, {%8,%9}, {%0,%1,%2,%3};"
        : "+f"(d[0]), "+f"(d[1]), "+f"(d[2]), "+f"(d[3])
        : "r"(a[0]), "r"(a[1]), "r"(a[2]), "r"(a[3]), "r"(b0), "r"(b1));
}

// ---------------------------------------------------------------------------
// Stage 1: masked global average pool.
// ---------------------------------------------------------------------------
__global__ void gap_kernel(const float* __restrict__ x, const int* __restrict__ lens) {
    int bc = blockIdx.x;
    const float4* row = reinterpret_cast<const float4*>(x + (size_t)bc * Tn);
    float s = 0.f;
    for (int i = threadIdx.x; i < Tn / 4; i += blockDim.x) {
        float4 v = row[i];
        s += (v.x + v.y) + (v.z + v.w);
    }
    for (int o = 16; o; o >>= 1) s += __shfl_down_sync(0xffffffffu, s, o);
    __shared__ float sm[8];
    int w = threadIdx.x >> 5, l = threadIdx.x & 31;
    if (l == 0) sm[w] = s;
    __syncthreads();
    if (threadIdx.x == 0) {
        float tot = 0.f;
        #pragma unroll
        for (int i = 0; i < 8; i++) tot += sm[i];
        g_gap[bc] = tot / (float)lens[bc / Cn];
    }
}

// ---------------------------------------------------------------------------
// Stage 2: h = sigmoid(gap @ w1^T + b1)
// ---------------------------------------------------------------------------
__global__ void fc1_kernel(const float* __restrict__ w1, const float* __restrict__ b1) {
    int b = blockIdx.x;
    __shared__ float sg[Cn];
    if (threadIdx.x < Cn) sg[threadIdx.x] = g_gap[b * Cn + threadIdx.x];
    __syncthreads();
    int j = threadIdx.x;
    const float* wr = w1 + (size_t)j * Cn;
    float z = b1[j];
    #pragma unroll 8
    for (int c = 0; c < Cn; c++) z += sg[c] * wr[c];
    g_h[b * MCn + j] = 1.f / (1.f + expf(-z));
}

// ---------------------------------------------------------------------------
// Stage 2.5: dynamic weights -> tf32 hi (rounded), FRAGMENT-PACKED A tiles.
// Frag values (a0..a3) = W[o][kk], W[o+8][kk], W[o][kk+4], W[o+8][kk+4].
// ---------------------------------------------------------------------------
__global__ void wd_kernel(const float* __restrict__ w2) {
    int idx = blockIdx.x * 256 + threadIdx.x;   // Bn*NCHUNK*4*8*32 total
    int lane = idx & 31;
    int og   = (idx >> 5) & 7;
    int ks   = (idx >> 8) & 3;
    int r    = idx >> 10;
    int c    = r % NCHUNK;
    int b    = r / NCHUNK;
    int g = lane >> 2, tig = lane & 3;

    int o0 = og * 16 + g;
    int kk0 = ks * 8 + tig;
    float hv[4];
    #pragma unroll
    for (int q = 0; q < 4; q++) {
        int o  = o0 + (q & 1) * 8;
        int kk = kk0 + (q >> 1) * 4;
        int ik = c * KC + kk;
        int i  = ik / 5;
        float v = w2[o * KTOT + ik] * g_h[b * MCn + 2 * o + (i >= 64 ? 1 : 0)];
        hv[q] = __uint_as_float(tf32_of(v));
    }
    float* base = g_wa + (size_t)(b * NCHUNK + c) * ATILE;
    int off = (ks * 8 + og) * 128 + lane * 4;
    *reinterpret_cast<float4*>(base + off) = make_float4(hv[0], hv[1], hv[2], hv[3]);
}

// ---------------------------------------------------------------------------
// Stage 3: implicit-GEMM conv via mma.sync tf32, single plane.
// Block: 128 o x 256 t, 16 warps of 64 o x 32 t, 512 thr, 1 CTA/SM.
// Panel = raw x rows (cp.async, HW tf32-truncated), 1 sync/chunk.
// ---------------------------------------------------------------------------
__global__ void __launch_bounds__(512, 1)
conv_kernel(const float* __restrict__ x, float* __restrict__ out) {
    extern __shared__ __align__(16) float smem[];
    float* sA = smem;                    // [2 buf][ATILE]
    float* sP = smem + PANEL_OFF;        // [2 buf][PPLANE]

    const int tid = threadIdx.x;
    const int t0 = blockIdx.x * BT;
    const int b  = blockIdx.y;
    const int w  = tid >> 5, lane = tid & 31;
    const int g  = lane >> 2, tig = lane & 3;
    const int m0 = (w & 1) * 64;
    const int og0 = m0 >> 4;             // 0 or 4
    const int n0 = (w >> 1) * 32;        // 0..224

    const float* xb   = x + (size_t)b * Cn * Tn;
    const float* wa_b = g_wa + (size_t)b * NCHUNK * ATILE;

    float acc[4][4][4];
    #pragma unroll
    for (int mt = 0; mt < 4; mt++)
        #pragma unroll
        for (int nt = 0; nt < 4; nt++)
            #pragma unroll
            for (int q = 0; q < 4; q++) acc[mt][nt][q] = 0.f;

    // ---- panel fill: 8 rows x 66 16B-chunks of raw x, via cp.async ----
    auto fill_panel = [&](int cc, int pb) {
        int i0 = (KC * cc) / 5;
        float* pH = sP + pb * PPLANE;
        for (int q = tid; q < 8 * 66; q += 512) {
            int row = q / 66;
            int col = (q - row * 66) * 4;          // float offset in row
            int i = i0 + row;
            int t = t0 - 4 + col;
            float* dst = pH + row * PRS + col;
            if (i < Cn && t >= 0 && t + 4 <= Tn) {
                uint32_t du;
                asm("{ .reg .u64 u; cvta.to.shared.u64 u, %1; cvt.u32.u64 %0, u; }"
                    : "=r"(du) : "l"(dst));
                asm volatile("cp.async.ca.shared.global [%0], [%1], 16;"
                             :: "r"(du), "l"(xb + (size_t)i * Tn + t) : "memory");
            } else {
                #pragma unroll
                for (int j = 0; j < 4; j++) {
                    int tt = t + j;
                    dst[j] = (i < Cn && tt >= 0 && tt < Tn)
                             ? __ldg(xb + (size_t)i * Tn + tt) : 0.f;
                }
            }
        }
    };
    auto prefetch_A = [&](int cc, int ab) {
        const float4* src = reinterpret_cast<const float4*>(wa_b + (size_t)cc * ATILE);
        float* dst = sA + ab * ATILE;
        #pragma unroll
        for (int e = 0; e < 2; e++) {
            uint32_t du;
            asm("{ .reg .u64 u; cvta.to.shared.u64 u, %1; cvt.u32.u64 %0, u; }"
                : "=r"(du) : "l"(dst + (e * 512 + tid) * 4));
            asm volatile("cp.async.cg.shared.global [%0], [%1], 16;"
                         :: "r"(du), "l"(src + e * 512 + tid) : "memory");
        }
    };

    // prologue
    prefetch_A(0, 0);
    fill_panel(0, 0);
    asm volatile("cp.async.commit_group;" ::: "memory");

    for (int c = 0; c < NCHUNK; c++) {
        const int buf = c & 1;
        asm volatile("cp.async.wait_group 0;" ::: "memory");
        __syncthreads();   // A(c)+panel(c) visible; MMA(c-1) reads retired

        if (c + 1 < NCHUNK) {
            prefetch_A(c + 1, buf ^ 1);
            fill_panel(c + 1, buf ^ 1);
            asm volatile("cp.async.commit_group;" ::: "memory");
        }

        const float* Ab = sA + buf * ATILE;
        const float* pH = sP + buf * PPLANE;
        const int i0 = (KC * c) / 5;

        #pragma unroll
        for (int ks = 0; ks < 4; ks++) {
            // per-thread B addresses: panel col for time (t0 + n + k - 2) is n + k + 2
            int ik0 = c * KC + ks * 8 + tig;
            int ik1 = ik0 + 4;
            int ia = ik0 / 5, ka = ik0 - ia * 5;
            int ib = ik1 / 5, kb2 = ik1 - ib * 5;
            int offB0 = (ia - i0) * PRS + ka + 2 + n0 + g;
            int offB1 = (ib - i0) * PRS + kb2 + 2 + n0 + g;

            uint32_t aH[4][4];
            #pragma unroll
            for (int mt = 0; mt < 4; mt++) {
                float4 fa = *reinterpret_cast<const float4*>(
                    Ab + (ks * 8 + og0 + mt) * 128 + lane * 4);
                aH[mt][0] = __float_as_uint(fa.x);
                aH[mt][1] = __float_as_uint(fa.y);
                aH[mt][2] = __float_as_uint(fa.z);
                aH[mt][3] = __float_as_uint(fa.w);
            }
            #pragma unroll
            for (int nt = 0; nt < 4; nt++) {
                uint32_t b0h = __float_as_uint(pH[offB0 + nt * 8]);
                uint32_t b1h = __float_as_uint(pH[offB1 + nt * 8]);
                #pragma unroll
                for (int mt = 0; mt < 4; mt++)
                    mma_tf32(acc[mt][nt], aH[mt], b0h, b1h);
            }
        }
    }

    // Epilogue
    #pragma unroll
    for (int mt = 0; mt < 4; mt++) {
        int o = m0 + mt * 16 + g;
        float* row0 = out + (size_t)(b * Cn + o) * Tn + t0;
        float* row1 = row0 + 8 * Tn;
        #pragma unroll
        for (int nt = 0; nt < 4; nt++) {
            int tcol = n0 + nt * 8 + tig * 2;
            reinterpret_cast<float2*>(row0 + tcol)[0] =
                make_float2(acc[mt][nt][0], acc[mt][nt][1]);
            reinterpret_cast<float2*>(row1 + tcol)[0] =
                make_float2(acc[mt][nt][2], acc[mt][nt][3]);
        }
    }
}

// ---------------------------------------------------------------------------
extern "C" void kernel_launch(void* const* d_in, const int* in_sizes, int n_in,
                              void* d_out, int out_size) {
    const float* x    = (const float*)d_in[0];
    const int*   lens = (const int*)  d_in[1];
    const float* w1   = (const float*)d_in[2];
    const float* b1   = (const float*)d_in[3];
    const float* w2   = (const float*)d_in[4];
    float* out = (float*)d_out;

    cudaFuncSetAttribute(conv_kernel,
                         cudaFuncAttributeMaxDynamicSharedMemorySize, SMEM_BYTES);

    gap_kernel<<<Bn * Cn, 256>>>(x, lens);
    fc1_kernel<<<Bn, 256>>>(w1, b1);
    wd_kernel<<<(Bn * NCHUNK * 4 * 8 * 32) / 256, 256>>>(w2);
    conv_kernel<<<dim3(NBLK, Bn), 512, SMEM_BYTES>>>(x, out);
}